// round 13
// baseline (speedup 1.0000x reference)
#include <cuda_runtime.h>
#include <cstdint>
#include <cstddef>

// ============================================================================
// Compile-time basis construction
// ============================================================================
__host__ __device__ constexpr double cexp_(double v) {
    double t = 1.0, s = 1.0;
    for (int n = 1; n < 90; ++n) { t *= v / n; s += t; }
    return s;
}
__host__ __device__ constexpr double csqrt_(double v) {
    if (v <= 0.0) return 0.0;
    double x = v < 1.0 ? 1.0 : v;
    for (int i = 0; i < 80; ++i) x = 0.5 * (x + v / x);
    return x;
}

struct Basis {
    float b0[3][5][5];
    float br[3][2][5][5];
    float bi[3][2][5][5];
};

__host__ __device__ constexpr Basis make_basis() {
    Basis B{};
    for (int yy = 0; yy < 5; ++yy) {
        for (int xx = 0; xx < 5; ++xx) {
            double ys = yy - 2.0, xs = xx - 2.0;
            double r = csqrt_(ys * ys + xs * xs);
            double cth = r > 0.0 ? xs / r : 1.0;
            double sth = r > 0.0 ? ys / r : 0.0;
            double ring0 = cexp_(-(r - 0.0) * (r - 0.0) / 0.72);
            double ring1 = cexp_(-(r - 1.0) * (r - 1.0) / 0.72);
            double ring2 = cexp_(-(r - 2.0) * (r - 2.0) / 0.72);
            B.b0[0][yy][xx] = (float)ring0;
            B.b0[1][yy][xx] = (float)ring1;
            B.b0[2][yy][xx] = (float)ring2;
            double ck = cth, sk = sth;
            for (int k = 0; k < 3; ++k) {
                B.br[k][0][yy][xx] = (float)(ring1 * ck);
                B.br[k][1][yy][xx] = (float)(ring2 * ck);
                B.bi[k][0][yy][xx] = (float)(ring1 * sk);
                B.bi[k][1][yy][xx] = (float)(ring2 * sk);
                double cn = ck * cth - sk * sth;
                double sn = sk * cth + ck * sth;
                ck = cn; sk = sn;
            }
        }
    }
    return B;
}

#define FMA2(acc, a, b) \
    asm("fma.rn.f32x2 %0, %1, %2, %0;" : "+l"(acc) : "l"(a), "l"(b))
#define SPLAT2(dst, f) \
    asm("mov.b64 %0, {%1, %1};" : "=l"(dst) : "f"(f))

// ============================================================================
// Fused kernel. CTA = 16x16 input tile -> 32x32 output tile, one oh half.
// smem: xs[32][360] 46080B | ysm[72][360] 103680B | ws[8][322] 10304B
//       smR[1024] 4096B | smCS[1024] float2 8192B     total 172352B
// Phase B idle threads (tid>=720) stage the per-pixel modulation table.
// ============================================================================
__device__ __forceinline__ float dotT(const float (&T)[5][5],
                                      const float (&w)[3][3],
                                      int SY, int SX) {
    float s = 0.f;
#pragma unroll
    for (int dy = 0; dy < 3; ++dy) {
        if (dy < SY) continue;
        int vy = (SY ? 5 : 4) - 2 * dy;
#pragma unroll
        for (int dx = 0; dx < 3; ++dx) {
            if (dx < SX) continue;
            int vx = (SX ? 5 : 4) - 2 * dx;
            float cf = T[vy][vx];
            if (cf != 0.f) s += cf * w[dy][dx];
        }
    }
    return s;
}

__global__ __launch_bounds__(1024, 1) void fused(const float* __restrict__ x,
                                                 const float* __restrict__ wts,
                                                 const float* __restrict__ alpha,
                                                 const float* __restrict__ bias,
                                                 float* __restrict__ out) {
    constexpr Basis BAS = make_basis();
    extern __shared__ float sm[];
    float*  xs   = sm;                         // [32][360]
    float*  ysm  = sm + 32 * 360;              // [72][360]
    float*  ws   = sm + (32 + 72) * 360;       // [8][322]
    float*  smR  = sm + (32 + 72) * 360 + 8 * 322;        // [1024]
    float2* smCS = (float2*)(smR + 1024);                  // [1024]

    const int tx = blockIdx.x, ty = blockIdx.y;
    const int n  = blockIdx.z >> 1;
    const int oh = blockIdx.z & 1;
    const int tid = threadIdx.x;
    const int ix0 = tx * 16, iy0 = ty * 16;

    // ---- Phase A: stage weights (channel-paired, pitch 10) + x tile -------
    for (int e = tid; e < 2560; e += 1024) {
        int o = e / 320, r = e % 320, i = r / 10, c = r % 10;
        ws[o * 322 + i * 10 + c] =
            (c < 9) ? wts[(oh * 8 + o) * 288 + i * 9 + c] : 0.f;
    }
    const float* xg = x + (size_t)n * 32 * 36864;
    const bool interior = (tx > 0) & (tx < 11) & (ty > 0) & (ty < 11);
    if (interior) {
        for (int e = tid; e < 10368; e += 1024) {
            int i = e / 324, rem = e % 324, r = rem / 18, cc = rem % 18;
            xs[i * 360 + r * 20 + cc] =
                xg[(size_t)i * 36864 + (iy0 - 1 + r) * 192 + (ix0 - 1 + cc)];
        }
    } else {
        for (int e = tid; e < 10368; e += 1024) {
            int i = e / 324, rem = e % 324, r = rem / 18, cc = rem % 18;
            int gy = iy0 - 1 + r, gx = ix0 - 1 + cc;
            float v = 0.f;
            if ((unsigned)gy < 192u && (unsigned)gx < 192u)
                v = xg[(size_t)i * 36864 + gy * 192 + gx];
            xs[i * 360 + r * 20 + cc] = v;
        }
    }
    __syncthreads();

    // ---- Phase B: channel mix (tid<720) | modulation staging (tid>=720) ---
    {
        const int o1 = tid & 7;
        const int pg = tid >> 3;
        if (pg < 90) {
            const int px0 = pg * 4;
            unsigned long long acc2[5][4];
#pragma unroll
            for (int p = 0; p < 5; ++p)
#pragma unroll
                for (int j = 0; j < 4; ++j) acc2[p][j] = 0ULL;

            const float* xp = xs + px0;
            const float* wg = ws + o1 * 322;

#pragma unroll 4
            for (int i = 0; i < 32; ++i) {
                float4 xv = *(const float4*)(xp + i * 360);
                unsigned long long x0, x1, x2, x3;
                SPLAT2(x0, xv.x); SPLAT2(x1, xv.y);
                SPLAT2(x2, xv.z); SPLAT2(x3, xv.w);
                unsigned long long xa[4] = {x0, x1, x2, x3};
#pragma unroll
                for (int p = 0; p < 5; ++p) {
                    unsigned long long w2 =
                        *(const unsigned long long*)(wg + i * 10 + p * 2);
#pragma unroll
                    for (int j = 0; j < 4; ++j) FMA2(acc2[p][j], w2, xa[j]);
                }
            }

            float* yb = ysm + o1 * 9 * 360 + px0;
#pragma unroll
            for (int p = 0; p < 5; ++p) {
                float lo[4], hi[4];
#pragma unroll
                for (int j = 0; j < 4; ++j) {
                    uint2 u = *(uint2*)&acc2[p][j];
                    lo[j] = __uint_as_float(u.x);
                    hi[j] = __uint_as_float(u.y);
                }
                *(float4*)(yb + (size_t)(2 * p) * 360) =
                    make_float4(lo[0], lo[1], lo[2], lo[3]);
                if (p < 4)
                    *(float4*)(yb + (size_t)(2 * p + 1) * 360) =
                        make_float4(hi[0], hi[1], hi[2], hi[3]);
            }
        } else {
            // modulation staging: rho, c1, s1 for all 1024 output px
            const int idx = tid - 720;   // 0..303
            const float* a0b = alpha + (size_t)n * 147456;
            const float* a1b = a0b + (size_t)8 * 147456;
            for (int e = idx; e < 1024; e += 304) {
                int pyy = e >> 5, pxx = e & 31;
                size_t go = (size_t)(ty * 32 + pyy) * 384 + tx * 32 + pxx;
                float a0 = a0b[go];
                float a1 = a1b[go];
                float rho = sqrtf(a0 * a0 + a1 * a1);
                float inv = 1.0f / (rho + 1e-8f);
                smR[e] = rho;
                smCS[e] = make_float2(a0 * inv, a1 * inv);
            }
        }
    }
    __syncthreads();

    // ---- Phase C: taps + modulation + rho/bias epilogue -------------------
    const int q  = tid & 255;
    const int os = tid >> 8;       // 0..3, 2 ol each
    const int qy = q >> 4, qx = q & 15;
    const int py0 = ty * 32 + 2 * qy;
    const int px0 = tx * 32 + 2 * qx;
    const int e00 = (2 * qy) * 32 + 2 * qx;   // modulation table index

#pragma unroll
    for (int oi = 0; oi < 2; ++oi) {
        const int ol = os * 2 + oi;
        const int o  = oh * 8 + ol;
        float acc[2][2] = {{0.f, 0.f}, {0.f, 0.f}};
        float ck[2][2], sk[2][2];
#pragma unroll
        for (int sy = 0; sy < 2; ++sy)
#pragma unroll
            for (int sx = 0; sx < 2; ++sx) {
                float2 cs = smCS[e00 + sy * 32 + sx];
                ck[sy][sx] = cs.x; sk[sy][sx] = cs.y;
            }

#pragma unroll
        for (int c = 0; c < 9; ++c) {
            if (c == 5 || c == 7) {
#pragma unroll
                for (int sy = 0; sy < 2; ++sy)
#pragma unroll
                    for (int sx = 0; sx < 2; ++sx) {
                        float2 cs = smCS[e00 + sy * 32 + sx];
                        float cn = ck[sy][sx] * cs.x - sk[sy][sx] * cs.y;
                        float sn = sk[sy][sx] * cs.x + ck[sy][sx] * cs.y;
                        ck[sy][sx] = cn; sk[sy][sx] = sn;
                    }
            }
            const float* wbp = ysm + (ol * 9 + c) * 360 + qy * 20 + qx;
            float w[3][3];
#pragma unroll
            for (int dy = 0; dy < 3; ++dy)
#pragma unroll
                for (int dx = 0; dx < 3; ++dx) w[dy][dx] = wbp[dy * 20 + dx];

            if (c < 3) {
                acc[0][0] += dotT(BAS.b0[c], w, 0, 0);
                acc[0][1] += dotT(BAS.b0[c], w, 0, 1);
                acc[1][0] += dotT(BAS.b0[c], w, 1, 0);
                acc[1][1] += dotT(BAS.b0[c], w, 1, 1);
            } else {
                const int k = (c - 3) >> 1;
                const int j = (c - 3) & 1;
#pragma unroll
                for (int sy = 0; sy < 2; ++sy)
#pragma unroll
                    for (int sx = 0; sx < 2; ++sx) {
                        float dR = dotT(BAS.br[k][j], w, sy, sx);
                        float dI = dotT(BAS.bi[k][j], w, sy, sx);
                        acc[sy][sx] += dR * ck[sy][sx] + dI * sk[sy][sx];
                    }
            }
        }
        float bo = bias[o];
#pragma unroll
        for (int sy = 0; sy < 2; ++sy) {
            float2 v;
            v.x = smR[e00 + sy * 32 + 0] * acc[sy][0] + bo;
            v.y = smR[e00 + sy * 32 + 1] * acc[sy][1] + bo;
            *(float2*)(out + ((size_t)(n * 16 + o)) * 147456 +
                       (size_t)(py0 + sy) * 384 + px0) = v;
        }
    }
}

// ============================================================================
// Launch
// ============================================================================
extern "C" void kernel_launch(void* const* d_in, const int* in_sizes, int n_in,
                              void* d_out, int out_size) {
    const float* x     = (const float*)d_in[0];  // (8,32,192,192)
    const float* alpha = (const float*)d_in[1];  // (2,8,1,384,384)
    const float* wts   = (const float*)d_in[2];  // (16,32,9)
    const float* bias  = (const float*)d_in[3];  // (16,)
    float* out = (float*)d_out;                  // (8,16,384,384)

    (void)in_sizes; (void)n_in; (void)out_size;

    const int smem = ((32 + 72) * 360 + 8 * 322 + 1024 + 2048) * 4;  // 172352 B
    cudaFuncSetAttribute(fused, cudaFuncAttributeMaxDynamicSharedMemorySize, smem);

    fused<<<dim3(12, 12, 16), 1024, smem>>>(x, wts, alpha, bias, out);
}